// round 4
// baseline (speedup 1.0000x reference)
#include <cuda_runtime.h>

#define NODES   50000
#define EDGES   1600000
#define INCH    128
#define HC      128      // HEADS * OUT_CH
#define HEADS   4
#define OUTCH   32
#define NEG     0.2f

// ---------------- device scratch (no allocs allowed) ----------------
__device__ float g_h[NODES * HC];        // transformed features  [N,128]
__device__ float g_asrc[NODES * HEADS];  // per-node src attention logits
__device__ float g_adst[NODES * HEADS];  // per-node dst attention logits
__device__ float g_s[NODES * HEADS];     // softmax denominators (unnormalized)

// ---------------- K0: zero accumulators ----------------
__global__ void k_zero(float* __restrict__ out, int n_out_f4) {
    int stride = gridDim.x * blockDim.x;
    int i = blockIdx.x * blockDim.x + threadIdx.x;
    float4 z = make_float4(0.f, 0.f, 0.f, 0.f);
    for (int idx = i; idx < n_out_f4; idx += stride)
        ((float4*)out)[idx] = z;
    for (int idx = i; idx < NODES * HEADS; idx += stride)
        g_s[idx] = 0.f;
}

// ---------------- K1: h = x @ W, fused attention dot products ----------------
// Block: 256 threads = 8 node-groups (warps) x 32 col-threads.
// Each warp handles 4 nodes; each lane owns 4 output columns (one float4).
// W (64KB) + x tile (16KB) in dynamic smem.
__global__ void k_gemm(const float* __restrict__ x, const float* __restrict__ W,
                       const float* __restrict__ attS, const float* __restrict__ attD,
                       int n) {
    extern __shared__ float sm[];
    float* Ws = sm;                 // [128][128]
    float* xs = sm + INCH * HC;     // [32][128]

    int tid = threadIdx.x;

    // load W into smem (4096 float4, 256 threads -> 16 iters)
    for (int i = tid; i < (INCH * HC) / 4; i += 256)
        ((float4*)Ws)[i] = ((const float4*)W)[i];

    int nodeBase = blockIdx.x * 32;
    // load x tile (1024 float4)
    for (int i = tid; i < (32 * INCH) / 4; i += 256) {
        int node = nodeBase + (i >> 5);
        float4 v = (node < n) ? ((const float4*)x)[node * 32 + (i & 31)]
                              : make_float4(0.f, 0.f, 0.f, 0.f);
        ((float4*)xs)[i] = v;
    }
    __syncthreads();

    int colt = tid & 31;   // lane: owns columns colt*4 .. colt*4+3
    int ng   = tid >> 5;   // warp: node group
    int head = colt >> 3;  // 4 consecutive cols always inside one head

    float4 aS = ((const float4*)attS)[colt];
    float4 aD = ((const float4*)attD)[colt];

    float acc[4][4];
#pragma unroll
    for (int i = 0; i < 4; i++)
#pragma unroll
        for (int j = 0; j < 4; j++) acc[i][j] = 0.f;

    const float* xr = xs + ng * 4 * INCH;
#pragma unroll 8
    for (int k = 0; k < INCH; k++) {
        float4 wv = ((const float4*)Ws)[k * 32 + colt];
#pragma unroll
        for (int i = 0; i < 4; i++) {
            float xv = xr[i * INCH + k];
            acc[i][0] += xv * wv.x;
            acc[i][1] += xv * wv.y;
            acc[i][2] += xv * wv.z;
            acc[i][3] += xv * wv.w;
        }
    }

#pragma unroll
    for (int i = 0; i < 4; i++) {
        int node = nodeBase + ng * 4 + i;
        float ds = acc[i][0] * aS.x + acc[i][1] * aS.y + acc[i][2] * aS.z + acc[i][3] * aS.w;
        float dd = acc[i][0] * aD.x + acc[i][1] * aD.y + acc[i][2] * aD.z + acc[i][3] * aD.w;
        // segmented reduce within 8-lane head groups
#pragma unroll
        for (int off = 1; off < 8; off <<= 1) {
            ds += __shfl_xor_sync(0xffffffffu, ds, off, 8);
            dd += __shfl_xor_sync(0xffffffffu, dd, off, 8);
        }
        if (node < n) {
            ((float4*)g_h)[node * 32 + colt] =
                make_float4(acc[i][0], acc[i][1], acc[i][2], acc[i][3]);
            if ((colt & 7) == 0) {
                g_asrc[node * HEADS + head] = ds;
                g_adst[node * HEADS + head] = dd;
            }
        }
    }
}

// ---------------- K2: single edge pass (unnormalized accumulate) ----------------
// warp per edge; lane -> (head = lane>>3, channels lane*4..lane*4+3)
// Edge index is INT32 (jax demotes int64 without x64 mode).
__device__ __forceinline__ void edge_body(float* __restrict__ out,
                                          int src, int dst, int lane, int head) {
    float a = __ldg(&g_asrc[src * HEADS + head]) +
              __ldg(&g_adst[dst * HEADS + head]);
    float t = a > 0.f ? a : NEG * a;
    float w = __expf(t);
    if ((lane & 7) == 0)
        atomicAdd(&g_s[dst * HEADS + head], w);
    float4 hv = __ldg(&((const float4*)g_h)[src * 32 + lane]);
    float* op = out + dst * HC + lane * 4;
    asm volatile("red.global.add.v4.f32 [%0], {%1,%2,%3,%4};"
                 :: "l"(op), "f"(w * hv.x), "f"(w * hv.y),
                    "f"(w * hv.z), "f"(w * hv.w));
}

__global__ void k_edge(const int* __restrict__ ei, float* __restrict__ out,
                       int ecnt) {
    int lane = threadIdx.x & 31;
    int head = lane >> 3;
    int gw = (blockIdx.x * blockDim.x + threadIdx.x) >> 5;
    int nwarps = (gridDim.x * blockDim.x) >> 5;

    const int* srcp = ei;
    const int* dstp = ei + ecnt;

    for (int e = gw * 2; e < ecnt; e += nwarps * 2) {
        // front-batch all index loads for MLP
        int s0 = __ldg(&srcp[e]);
        int d0 = __ldg(&dstp[e]);
        int s1 = 0, d1 = 0;
        bool has1 = (e + 1 < ecnt);
        if (has1) {
            s1 = __ldg(&srcp[e + 1]);
            d1 = __ldg(&dstp[e + 1]);
        }
        edge_body(out, s0, d0, lane, head);
        if (has1)
            edge_body(out, s1, d1, lane, head);
    }
}

// ---------------- K3: self-loop fold, normalize, bias, ELU ----------------
__global__ void k_final(float* __restrict__ out, const float* __restrict__ bias,
                        int n) {
    int lane = threadIdx.x & 31;
    int node = (blockIdx.x * blockDim.x + threadIdx.x) >> 5;
    if (node >= n) return;
    int head = lane >> 3;

    float a = g_asrc[node * HEADS + head] + g_adst[node * HEADS + head];
    float t = a > 0.f ? a : NEG * a;
    float w = __expf(t);                       // self-loop weight
    float inv = 1.f / (g_s[node * HEADS + head] + w);

    float4 o  = ((const float4*)out)[node * 32 + lane];
    float4 hv = ((const float4*)g_h)[node * 32 + lane];
    float4 b  = ((const float4*)bias)[lane];

    float v0 = (o.x + w * hv.x) * inv + b.x;
    float v1 = (o.y + w * hv.y) * inv + b.y;
    float v2 = (o.z + w * hv.z) * inv + b.z;
    float v3 = (o.w + w * hv.w) * inv + b.w;

    v0 = v0 > 0.f ? v0 : expm1f(v0);
    v1 = v1 > 0.f ? v1 : expm1f(v1);
    v2 = v2 > 0.f ? v2 : expm1f(v2);
    v3 = v3 > 0.f ? v3 : expm1f(v3);

    ((float4*)out)[node * 32 + lane] = make_float4(v0, v1, v2, v3);
}

// ---------------- launch ----------------
extern "C" void kernel_launch(void* const* d_in, const int* in_sizes, int n_in,
                              void* d_out, int out_size) {
    const float* x    = (const float*)d_in[0];
    const int*   ei   = (const int*)d_in[1];      // int32 (jax demotes int64)
    const float* W    = (const float*)d_in[2];
    const float* attS = (const float*)d_in[3];
    const float* attD = (const float*)d_in[4];
    const float* bias = (const float*)d_in[5];
    float*       out  = (float*)d_out;

    int n    = in_sizes[0] / INCH;     // 50000
    int ecnt = in_sizes[1] / 2;        // 1600000

    const int smemBytes = (INCH * HC + 32 * INCH) * (int)sizeof(float); // 80KB
    cudaFuncSetAttribute(k_gemm, cudaFuncAttributeMaxDynamicSharedMemorySize,
                         smemBytes);

    k_zero<<<512, 256>>>(out, (n * HC) / 4);
    k_gemm<<<(n + 31) / 32, 256, smemBytes>>>(x, W, attS, attD, n);
    k_edge<<<1184, 256>>>(ei, out, ecnt);
    k_final<<<(n * 32 + 255) / 256, 256>>>(out, bias, n);
}

// round 5
// speedup vs baseline: 1.5885x; 1.5885x over previous
#include <cuda_runtime.h>

#define NODES   50000
#define EDGES   1600000
#define INCH    128
#define HC      128      // HEADS * OUT_CH
#define HEADS   4
#define OUTCH   32
#define NEG     0.2f

// ---------------- device scratch (no allocs allowed) ----------------
__device__ float g_h[NODES * HC];        // transformed features  [N,128]
__device__ float g_asrc[NODES * HEADS];  // per-node src attention logits
__device__ float g_adst[NODES * HEADS];  // per-node dst attention logits
__device__ int   g_cnt[NODES];           // in-degree histogram
__device__ int   g_start[NODES];         // CSR start (exclusive prefix)
__device__ int   g_cur[NODES];           // scatter cursors
__device__ int   g_ssrc[EDGES];          // src indices sorted by dst

// ---------------- K0: zero histogram ----------------
__global__ void k_zero(int n) {
    int i = blockIdx.x * blockDim.x + threadIdx.x;
    int stride = gridDim.x * blockDim.x;
    for (; i < n; i += stride) g_cnt[i] = 0;
}

// ---------------- K1: h = x @ W, fused attention dot products ----------------
// 256 threads = 8 warps x 32 lanes; warp handles 4 nodes, lane owns 4 cols.
__global__ void k_gemm(const float* __restrict__ x, const float* __restrict__ W,
                       const float* __restrict__ attS, const float* __restrict__ attD,
                       int n) {
    extern __shared__ float sm[];
    float* Ws = sm;                 // [128][128]
    float* xs = sm + INCH * HC;     // [32][128]

    int tid = threadIdx.x;
    for (int i = tid; i < (INCH * HC) / 4; i += 256)
        ((float4*)Ws)[i] = ((const float4*)W)[i];

    int nodeBase = blockIdx.x * 32;
    for (int i = tid; i < (32 * INCH) / 4; i += 256) {
        int node = nodeBase + (i >> 5);
        float4 v = (node < n) ? ((const float4*)x)[node * 32 + (i & 31)]
                              : make_float4(0.f, 0.f, 0.f, 0.f);
        ((float4*)xs)[i] = v;
    }
    __syncthreads();

    int colt = tid & 31;
    int ng   = tid >> 5;
    int head = colt >> 3;

    float4 aS = ((const float4*)attS)[colt];
    float4 aD = ((const float4*)attD)[colt];

    float acc[4][4];
#pragma unroll
    for (int i = 0; i < 4; i++)
#pragma unroll
        for (int j = 0; j < 4; j++) acc[i][j] = 0.f;

    const float* xr = xs + ng * 4 * INCH;
#pragma unroll 8
    for (int k = 0; k < INCH; k++) {
        float4 wv = ((const float4*)Ws)[k * 32 + colt];
#pragma unroll
        for (int i = 0; i < 4; i++) {
            float xv = xr[i * INCH + k];
            acc[i][0] += xv * wv.x;
            acc[i][1] += xv * wv.y;
            acc[i][2] += xv * wv.z;
            acc[i][3] += xv * wv.w;
        }
    }

#pragma unroll
    for (int i = 0; i < 4; i++) {
        int node = nodeBase + ng * 4 + i;
        float ds = acc[i][0] * aS.x + acc[i][1] * aS.y + acc[i][2] * aS.z + acc[i][3] * aS.w;
        float dd = acc[i][0] * aD.x + acc[i][1] * aD.y + acc[i][2] * aD.z + acc[i][3] * aD.w;
#pragma unroll
        for (int off = 1; off < 8; off <<= 1) {
            ds += __shfl_xor_sync(0xffffffffu, ds, off, 8);
            dd += __shfl_xor_sync(0xffffffffu, dd, off, 8);
        }
        if (node < n) {
            ((float4*)g_h)[node * 32 + colt] =
                make_float4(acc[i][0], acc[i][1], acc[i][2], acc[i][3]);
            if ((colt & 7) == 0) {
                g_asrc[node * HEADS + head] = ds;
                g_adst[node * HEADS + head] = dd;
            }
        }
    }
}

// ---------------- K2: in-degree histogram ----------------
__global__ void k_hist(const int* __restrict__ dstp, int ecnt) {
    int i = blockIdx.x * blockDim.x + threadIdx.x;
    int stride = gridDim.x * blockDim.x;
    for (; i < ecnt; i += stride)
        atomicAdd(&g_cnt[__ldg(dstp + i)], 1);
}

// ---------------- K3: exclusive scan (single block, chunked) ----------------
__global__ void k_scan(int n) {
    __shared__ int wsum[32];
    __shared__ int carry_sh;
    int tid = threadIdx.x, lane = tid & 31, wid = tid >> 5;
    if (tid == 0) carry_sh = 0;
    __syncthreads();

    for (int base = 0; base < n; base += 1024) {
        int i = base + tid;
        int orig = (i < n) ? g_cnt[i] : 0;
        int v = orig;
#pragma unroll
        for (int off = 1; off < 32; off <<= 1) {
            int t = __shfl_up_sync(0xffffffffu, v, off);
            if (lane >= off) v += t;
        }
        if (lane == 31) wsum[wid] = v;
        __syncthreads();
        if (wid == 0) {
            int s = wsum[lane];
#pragma unroll
            for (int off = 1; off < 32; off <<= 1) {
                int t = __shfl_up_sync(0xffffffffu, s, off);
                if (lane >= off) s += t;
            }
            wsum[lane] = s;
        }
        __syncthreads();
        int carry = carry_sh;
        int excl = v - orig + (wid > 0 ? wsum[wid - 1] : 0) + carry;
        if (i < n) { g_start[i] = excl; g_cur[i] = excl; }
        __syncthreads();
        if (tid == 0) carry_sh = carry + wsum[31];
        __syncthreads();
    }
}

// ---------------- K4: scatter src into dst-sorted order ----------------
__global__ void k_scatter(const int* __restrict__ srcp,
                          const int* __restrict__ dstp, int ecnt) {
    int i = blockIdx.x * blockDim.x + threadIdx.x;
    int stride = gridDim.x * blockDim.x;
    for (; i < ecnt; i += stride) {
        int d = __ldg(dstp + i);
        int s = __ldg(srcp + i);
        int pos = atomicAdd(&g_cur[d], 1);
        g_ssrc[pos] = s;
    }
}

// ---------------- K5: warp-per-dst aggregation + fused epilogue ----------------
// lane -> (head = lane>>3, channels lane*4..lane*4+3); register accumulation;
// self-loop fold, softmax normalize, bias, ELU, single float4 store.
__global__ void k_agg(float* __restrict__ out, const float* __restrict__ bias,
                      int n) {
    int lane = threadIdx.x & 31;
    int node = (blockIdx.x * blockDim.x + threadIdx.x) >> 5;
    if (node >= n) return;
    int head = lane >> 3;

    float aD = __ldg(&g_adst[node * HEADS + head]);
    int start = __ldg(&g_start[node]);
    int deg   = __ldg(&g_cnt[node]);
    int end   = start + deg;

    float4 acc = make_float4(0.f, 0.f, 0.f, 0.f);
    float ssum = 0.f;

    int e = start;
    for (; e + 4 <= end; e += 4) {
        // front-batch: 4 index loads, 4 logit loads, 4 feature loads
        int s0 = __ldg(&g_ssrc[e]);
        int s1 = __ldg(&g_ssrc[e + 1]);
        int s2 = __ldg(&g_ssrc[e + 2]);
        int s3 = __ldg(&g_ssrc[e + 3]);
        float a0 = __ldg(&g_asrc[s0 * HEADS + head]) + aD;
        float a1 = __ldg(&g_asrc[s1 * HEADS + head]) + aD;
        float a2 = __ldg(&g_asrc[s2 * HEADS + head]) + aD;
        float a3 = __ldg(&g_asrc[s3 * HEADS + head]) + aD;
        float4 h0 = __ldg(&((const float4*)g_h)[s0 * 32 + lane]);
        float4 h1 = __ldg(&((const float4*)g_h)[s1 * 32 + lane]);
        float4 h2 = __ldg(&((const float4*)g_h)[s2 * 32 + lane]);
        float4 h3 = __ldg(&((const float4*)g_h)[s3 * 32 + lane]);
        float w0 = __expf(a0 > 0.f ? a0 : NEG * a0);
        float w1 = __expf(a1 > 0.f ? a1 : NEG * a1);
        float w2 = __expf(a2 > 0.f ? a2 : NEG * a2);
        float w3 = __expf(a3 > 0.f ? a3 : NEG * a3);
        ssum += w0 + w1 + w2 + w3;
        acc.x += w0 * h0.x + w1 * h1.x + w2 * h2.x + w3 * h3.x;
        acc.y += w0 * h0.y + w1 * h1.y + w2 * h2.y + w3 * h3.y;
        acc.z += w0 * h0.z + w1 * h1.z + w2 * h2.z + w3 * h3.z;
        acc.w += w0 * h0.w + w1 * h1.w + w2 * h2.w + w3 * h3.w;
    }
    for (; e < end; e++) {
        int s = __ldg(&g_ssrc[e]);
        float a = __ldg(&g_asrc[s * HEADS + head]) + aD;
        float w = __expf(a > 0.f ? a : NEG * a);
        float4 hv = __ldg(&((const float4*)g_h)[s * 32 + lane]);
        ssum += w;
        acc.x += w * hv.x; acc.y += w * hv.y;
        acc.z += w * hv.z; acc.w += w * hv.w;
    }

    // self loop
    {
        float a = __ldg(&g_asrc[node * HEADS + head]) + aD;
        float w = __expf(a > 0.f ? a : NEG * a);
        float4 hv = ((const float4*)g_h)[node * 32 + lane];
        ssum += w;
        acc.x += w * hv.x; acc.y += w * hv.y;
        acc.z += w * hv.z; acc.w += w * hv.w;
    }

    float inv = 1.f / ssum;
    float4 b = ((const float4*)bias)[lane];
    float v0 = acc.x * inv + b.x;
    float v1 = acc.y * inv + b.y;
    float v2 = acc.z * inv + b.z;
    float v3 = acc.w * inv + b.w;
    v0 = v0 > 0.f ? v0 : expm1f(v0);
    v1 = v1 > 0.f ? v1 : expm1f(v1);
    v2 = v2 > 0.f ? v2 : expm1f(v2);
    v3 = v3 > 0.f ? v3 : expm1f(v3);
    ((float4*)out)[node * 32 + lane] = make_float4(v0, v1, v2, v3);
}

// ---------------- launch ----------------
extern "C" void kernel_launch(void* const* d_in, const int* in_sizes, int n_in,
                              void* d_out, int out_size) {
    const float* x    = (const float*)d_in[0];
    const int*   ei   = (const int*)d_in[1];      // int32 (jax demotes int64)
    const float* W    = (const float*)d_in[2];
    const float* attS = (const float*)d_in[3];
    const float* attD = (const float*)d_in[4];
    const float* bias = (const float*)d_in[5];
    float*       out  = (float*)d_out;

    int n    = in_sizes[0] / INCH;     // 50000
    int ecnt = in_sizes[1] / 2;        // 1600000

    const int smemBytes = (INCH * HC + 32 * INCH) * (int)sizeof(float); // 80KB
    cudaFuncSetAttribute(k_gemm, cudaFuncAttributeMaxDynamicSharedMemorySize,
                         smemBytes);

    k_zero<<<64, 1024>>>(n);
    k_gemm<<<(n + 31) / 32, 256, smemBytes>>>(x, W, attS, attD, n);
    k_hist<<<2048, 256>>>(ei + ecnt, ecnt);
    k_scan<<<1, 1024>>>(n);
    k_scatter<<<2048, 256>>>(ei, ei + ecnt, ecnt);
    k_agg<<<(n + 7) / 8, 256>>>(out, bias, n);
}

// round 6
// speedup vs baseline: 1.7236x; 1.0850x over previous
#include <cuda_runtime.h>
#include <cuda_fp16.h>

#define NODES   50000
#define EDGES   1600000
#define INCH    128
#define HC      128      // HEADS * OUT_CH
#define HEADS   4
#define OUTCH   32
#define NEG     0.2f
#define NSCANB  ((NODES + 1023) / 1024)   // 49

// ---------------- device scratch (no allocs allowed) ----------------
__device__ float g_h[NODES * HC];         // transformed features fp32 [N,128]
__device__ uint2 g_hh[NODES * HC / 4];    // fp16x8 packed copy of h (per lane: 4 ch)
__device__ float g_asrc[NODES * HEADS];   // per-node src attention logits
__device__ float g_adst[NODES * HEADS];   // per-node dst attention logits
__device__ int   g_cnt[NODES];            // in-degree histogram
__device__ int   g_start[NODES];          // CSR start (exclusive prefix)
__device__ int   g_cur[NODES];            // scatter cursors
__device__ int   g_bsum[NSCANB];          // per-block scan sums
__device__ int   g_ssrc[EDGES];           // src indices sorted by dst

// ---------------- K0: zero histogram ----------------
__global__ void k_zero(int n) {
    int i = blockIdx.x * blockDim.x + threadIdx.x;
    int stride = gridDim.x * blockDim.x;
    for (; i < n; i += stride) g_cnt[i] = 0;
}

// ---------------- K1: h = x @ W, fused attention dot products ----------------
__global__ void k_gemm(const float* __restrict__ x, const float* __restrict__ W,
                       const float* __restrict__ attS, const float* __restrict__ attD,
                       int n) {
    extern __shared__ float sm[];
    float* Ws = sm;                 // [128][128]
    float* xs = sm + INCH * HC;     // [32][128]

    int tid = threadIdx.x;
    for (int i = tid; i < (INCH * HC) / 4; i += 256)
        ((float4*)Ws)[i] = ((const float4*)W)[i];

    int nodeBase = blockIdx.x * 32;
    for (int i = tid; i < (32 * INCH) / 4; i += 256) {
        int node = nodeBase + (i >> 5);
        float4 v = (node < n) ? ((const float4*)x)[node * 32 + (i & 31)]
                              : make_float4(0.f, 0.f, 0.f, 0.f);
        ((float4*)xs)[i] = v;
    }
    __syncthreads();

    int colt = tid & 31;
    int ng   = tid >> 5;
    int head = colt >> 3;

    float4 aS = ((const float4*)attS)[colt];
    float4 aD = ((const float4*)attD)[colt];

    float acc[4][4];
#pragma unroll
    for (int i = 0; i < 4; i++)
#pragma unroll
        for (int j = 0; j < 4; j++) acc[i][j] = 0.f;

    const float* xr = xs + ng * 4 * INCH;
#pragma unroll 8
    for (int k = 0; k < INCH; k++) {
        float4 wv = ((const float4*)Ws)[k * 32 + colt];
#pragma unroll
        for (int i = 0; i < 4; i++) {
            float xv = xr[i * INCH + k];
            acc[i][0] += xv * wv.x;
            acc[i][1] += xv * wv.y;
            acc[i][2] += xv * wv.z;
            acc[i][3] += xv * wv.w;
        }
    }

#pragma unroll
    for (int i = 0; i < 4; i++) {
        int node = nodeBase + ng * 4 + i;
        float ds = acc[i][0] * aS.x + acc[i][1] * aS.y + acc[i][2] * aS.z + acc[i][3] * aS.w;
        float dd = acc[i][0] * aD.x + acc[i][1] * aD.y + acc[i][2] * aD.z + acc[i][3] * aD.w;
#pragma unroll
        for (int off = 1; off < 8; off <<= 1) {
            ds += __shfl_xor_sync(0xffffffffu, ds, off, 8);
            dd += __shfl_xor_sync(0xffffffffu, dd, off, 8);
        }
        if (node < n) {
            ((float4*)g_h)[node * 32 + colt] =
                make_float4(acc[i][0], acc[i][1], acc[i][2], acc[i][3]);
            // packed fp16 copy for the edge-gather path
            __half2 lo = __floats2half2_rn(acc[i][0], acc[i][1]);
            __half2 hi = __floats2half2_rn(acc[i][2], acc[i][3]);
            uint2 u;
            u.x = reinterpret_cast<unsigned&>(lo);
            u.y = reinterpret_cast<unsigned&>(hi);
            g_hh[node * 32 + colt] = u;
            if ((colt & 7) == 0) {
                g_asrc[node * HEADS + head] = ds;
                g_adst[node * HEADS + head] = dd;
            }
        }
    }
}

// ---------------- K2: in-degree histogram ----------------
__global__ void k_hist(const int* __restrict__ dstp, int ecnt) {
    int i = blockIdx.x * blockDim.x + threadIdx.x;
    int stride = gridDim.x * blockDim.x;
    for (; i < ecnt; i += stride)
        atomicAdd(&g_cnt[__ldg(dstp + i)], 1);
}

// ---------------- K3a: per-block exclusive scan ----------------
__global__ void k_scan1(int n) {
    __shared__ int wsum[32];
    int tid = threadIdx.x, lane = tid & 31, wid = tid >> 5;
    int i = blockIdx.x * 1024 + tid;
    int orig = (i < n) ? g_cnt[i] : 0;
    int v = orig;
#pragma unroll
    for (int off = 1; off < 32; off <<= 1) {
        int t = __shfl_up_sync(0xffffffffu, v, off);
        if (lane >= off) v += t;
    }
    if (lane == 31) wsum[wid] = v;
    __syncthreads();
    if (wid == 0) {
        int s = wsum[lane];
#pragma unroll
        for (int off = 1; off < 32; off <<= 1) {
            int t = __shfl_up_sync(0xffffffffu, s, off);
            if (lane >= off) s += t;
        }
        wsum[lane] = s;
    }
    __syncthreads();
    int excl = v - orig + (wid > 0 ? wsum[wid - 1] : 0);
    if (i < n) g_start[i] = excl;
    if (tid == 0) g_bsum[blockIdx.x] = wsum[31];
}

// ---------------- K3b: scan of block sums (64 threads, nb<=64) ----------------
__global__ void k_scan2(int nb) {
    __shared__ int t0;
    int tid = threadIdx.x, lane = tid & 31, w = tid >> 5;
    int orig = (tid < nb) ? g_bsum[tid] : 0;
    int v = orig;
#pragma unroll
    for (int off = 1; off < 32; off <<= 1) {
        int t = __shfl_up_sync(0xffffffffu, v, off);
        if (lane >= off) v += t;
    }
    if (w == 0 && lane == 31) t0 = v;
    __syncthreads();
    int incl = v + (w == 1 ? t0 : 0);
    if (tid < nb) g_bsum[tid] = incl - orig;   // exclusive
}

// ---------------- K3c: add block offsets, init cursors ----------------
__global__ void k_scan3(int n) {
    int i = blockIdx.x * 1024 + threadIdx.x;
    if (i < n) {
        int v = g_start[i] + g_bsum[blockIdx.x];
        g_start[i] = v;
        g_cur[i] = v;
    }
}

// ---------------- K4: scatter src into dst-sorted order ----------------
__global__ void k_scatter(const int* __restrict__ srcp,
                          const int* __restrict__ dstp, int ecnt) {
    int i = blockIdx.x * blockDim.x + threadIdx.x;
    int stride = gridDim.x * blockDim.x;
    for (; i < ecnt; i += stride) {
        int d = __ldg(dstp + i);
        int s = __ldg(srcp + i);
        int pos = atomicAdd(&g_cur[d], 1);
        g_ssrc[pos] = s;
    }
}

// ---------------- K5: warp-per-dst aggregation + fused epilogue ----------------
// fp16 gather of h; fp32 weights/accumulation; self-loop fp32.
__device__ __forceinline__ void fma_h16(float4& acc, float w, uint2 u) {
    __half2 lo = reinterpret_cast<__half2&>(u.x);
    __half2 hi = reinterpret_cast<__half2&>(u.y);
    float2 f01 = __half22float2(lo);
    float2 f23 = __half22float2(hi);
    acc.x += w * f01.x; acc.y += w * f01.y;
    acc.z += w * f23.x; acc.w += w * f23.y;
}

__global__ void k_agg(float* __restrict__ out, const float* __restrict__ bias,
                      int n) {
    int lane = threadIdx.x & 31;
    int node = (blockIdx.x * blockDim.x + threadIdx.x) >> 5;
    if (node >= n) return;
    int head = lane >> 3;

    float aD = __ldg(&g_adst[node * HEADS + head]);
    int start = __ldg(&g_start[node]);
    int deg   = __ldg(&g_cnt[node]);
    int end   = start + deg;

    float4 acc = make_float4(0.f, 0.f, 0.f, 0.f);
    float ssum = 0.f;

    int e = start;
    for (; e + 4 <= end; e += 4) {
        int s0 = __ldg(&g_ssrc[e]);
        int s1 = __ldg(&g_ssrc[e + 1]);
        int s2 = __ldg(&g_ssrc[e + 2]);
        int s3 = __ldg(&g_ssrc[e + 3]);
        float a0 = __ldg(&g_asrc[s0 * HEADS + head]) + aD;
        float a1 = __ldg(&g_asrc[s1 * HEADS + head]) + aD;
        float a2 = __ldg(&g_asrc[s2 * HEADS + head]) + aD;
        float a3 = __ldg(&g_asrc[s3 * HEADS + head]) + aD;
        uint2 u0 = __ldg(&g_hh[s0 * 32 + lane]);
        uint2 u1 = __ldg(&g_hh[s1 * 32 + lane]);
        uint2 u2 = __ldg(&g_hh[s2 * 32 + lane]);
        uint2 u3 = __ldg(&g_hh[s3 * 32 + lane]);
        float w0 = __expf(a0 > 0.f ? a0 : NEG * a0);
        float w1 = __expf(a1 > 0.f ? a1 : NEG * a1);
        float w2 = __expf(a2 > 0.f ? a2 : NEG * a2);
        float w3 = __expf(a3 > 0.f ? a3 : NEG * a3);
        ssum += w0 + w1 + w2 + w3;
        fma_h16(acc, w0, u0);
        fma_h16(acc, w1, u1);
        fma_h16(acc, w2, u2);
        fma_h16(acc, w3, u3);
    }
    for (; e < end; e++) {
        int s = __ldg(&g_ssrc[e]);
        float a = __ldg(&g_asrc[s * HEADS + head]) + aD;
        float w = __expf(a > 0.f ? a : NEG * a);
        uint2 u = __ldg(&g_hh[s * 32 + lane]);
        ssum += w;
        fma_h16(acc, w, u);
    }

    // self loop in fp32 (largest single weight: keep full precision)
    {
        float a = __ldg(&g_asrc[node * HEADS + head]) + aD;
        float w = __expf(a > 0.f ? a : NEG * a);
        float4 hv = ((const float4*)g_h)[node * 32 + lane];
        ssum += w;
        acc.x += w * hv.x; acc.y += w * hv.y;
        acc.z += w * hv.z; acc.w += w * hv.w;
    }

    float inv = 1.f / ssum;
    float4 b = ((const float4*)bias)[lane];
    float v0 = acc.x * inv + b.x;
    float v1 = acc.y * inv + b.y;
    float v2 = acc.z * inv + b.z;
    float v3 = acc.w * inv + b.w;
    v0 = v0 > 0.f ? v0 : expm1f(v0);
    v1 = v1 > 0.f ? v1 : expm1f(v1);
    v2 = v2 > 0.f ? v2 : expm1f(v2);
    v3 = v3 > 0.f ? v3 : expm1f(v3);
    ((float4*)out)[node * 32 + lane] = make_float4(v0, v1, v2, v3);
}

// ---------------- launch ----------------
extern "C" void kernel_launch(void* const* d_in, const int* in_sizes, int n_in,
                              void* d_out, int out_size) {
    const float* x    = (const float*)d_in[0];
    const int*   ei   = (const int*)d_in[1];      // int32 (jax demotes int64)
    const float* W    = (const float*)d_in[2];
    const float* attS = (const float*)d_in[3];
    const float* attD = (const float*)d_in[4];
    const float* bias = (const float*)d_in[5];
    float*       out  = (float*)d_out;

    int n    = in_sizes[0] / INCH;     // 50000
    int ecnt = in_sizes[1] / 2;        // 1600000
    int nb   = (n + 1023) / 1024;      // 49

    const int smemBytes = (INCH * HC + 32 * INCH) * (int)sizeof(float); // 80KB
    cudaFuncSetAttribute(k_gemm, cudaFuncAttributeMaxDynamicSharedMemorySize,
                         smemBytes);

    k_zero<<<64, 1024>>>(n);
    k_gemm<<<(n + 31) / 32, 256, smemBytes>>>(x, W, attS, attD, n);
    k_hist<<<2048, 256>>>(ei + ecnt, ecnt);
    k_scan1<<<nb, 1024>>>(n);
    k_scan2<<<1, 64>>>(nb);
    k_scan3<<<nb, 1024>>>(n);
    k_scatter<<<2048, 256>>>(ei, ei + ecnt, ecnt);
    k_agg<<<(n + 7) / 8, 256>>>(out, bias, n);
}